// round 4
// baseline (speedup 1.0000x reference)
#include <cuda_runtime.h>

// Interpolate1D: stride-2 linear upsample along dim 1.
// in:  [B=16, N=8192, C=256] fp32
// out: [B, 2N, C] fp32
//   out[b, 2k,   c] = x[b, k, c]
//   out[b, 2k+1, c] = 0.5*(x[b,k,c] + x[b,k+1,c])  (k < N-1)
//   out[b, 2N-1, c] = x[b, N-1, c]
//
// DRAM-bound at ~75% of 8 TB/s; this round: 32-bit indexing, block=512,
// plain stores (A/B vs .cs), 2 float4 chunks per thread.

namespace {
constexpr int B = 16;
constexpr int N = 8192;
constexpr int C4 = 64;                       // float4 per row (C=256)
constexpr int HALF = 32;                     // 2 chunks per thread
constexpr unsigned TOTALT = (unsigned)B * N * HALF;  // 4,194,304 (fits u32)
}

__global__ void __launch_bounds__(512)
interp1d_kernel(const float4* __restrict__ x, float4* __restrict__ y) {
    unsigned i = blockIdx.x * 512u + threadIdx.x;   // exact grid, no bounds check
    unsigned c  = i & (HALF - 1);                   // 0..31
    unsigned bn = i >> 5;                           // b*N + k  (< 131072)
    unsigned k  = bn & (N - 1);

    unsigned base = bn * C4 + c;                    // < 8.4M, fits u32
    float4 cur0 = x[base];
    float4 cur1 = x[base + HALF];
    unsigned nbase = (k < N - 1) ? base + C4 : base;
    float4 nxt0 = x[nbase];
    float4 nxt1 = x[nbase + HALF];

    float4 mid0, mid1;
    mid0.x = 0.5f * (cur0.x + nxt0.x);
    mid0.y = 0.5f * (cur0.y + nxt0.y);
    mid0.z = 0.5f * (cur0.z + nxt0.z);
    mid0.w = 0.5f * (cur0.w + nxt0.w);
    mid1.x = 0.5f * (cur1.x + nxt1.x);
    mid1.y = 0.5f * (cur1.y + nxt1.y);
    mid1.z = 0.5f * (cur1.z + nxt1.z);
    mid1.w = 0.5f * (cur1.w + nxt1.w);

    unsigned o = (bn << 1) * C4 + c;                // < 16.8M float4, fits u32
    y[o]             = cur0;
    y[o + HALF]      = cur1;
    y[o + C4]        = mid0;
    y[o + C4 + HALF] = mid1;
}

extern "C" void kernel_launch(void* const* d_in, const int* in_sizes, int n_in,
                              void* d_out, int out_size) {
    const float4* x = (const float4*)d_in[0];
    float4* y = (float4*)d_out;
    interp1d_kernel<<<TOTALT / 512, 512>>>(x, y);
}

// round 5
// speedup vs baseline: 1.0025x; 1.0025x over previous
#include <cuda_runtime.h>

// Interpolate1D: stride-2 linear upsample along dim 1.
// in:  [B=16, N=8192, C=256] fp32
// out: [B, 2N, C] fp32
//   out[b, 2k,   c] = x[b, k, c]
//   out[b, 2k+1, c] = 0.5*(x[b,k,c] + x[b,k+1,c])  (k < N-1)
//   out[b, 2N-1, c] = x[b, N-1, c]
//
// Row-paired: each thread owns one float4 column of input rows (2m, 2m+1),
// loading 3 row-chunks (cur0, cur1, nxt) and writing 4 contiguous output
// row-chunks. 3 loads / 4 stores per 2 rows (was 4/4).

namespace {
constexpr int B = 16;
constexpr int N = 8192;               // even, so row pairs never cross a batch
constexpr int C4 = 64;                // float4 per row (C=256)
constexpr unsigned TOTALT = (unsigned)B * (N / 2) * C4;  // 4,194,304
}

__global__ void __launch_bounds__(256)
interp1d_kernel(const float4* __restrict__ x, float4* __restrict__ y) {
    unsigned i = blockIdx.x * 256u + threadIdx.x;  // exact grid
    unsigned c = i & (C4 - 1);                     // float4 column 0..63
    unsigned m = i >> 6;                           // pair index: rows 2m, 2m+1
    unsigned k1 = (2u * m + 1u) & (N - 1);         // row index of cur1 within batch

    unsigned base = 2u * m * C4 + c;               // x[2m] chunk
    float4 cur0 = x[base];
    float4 cur1 = x[base + C4];
    float4 nxt  = (k1 < N - 1) ? x[base + 2u * C4] : cur1;

    float4 mid01, mid12;
    mid01.x = 0.5f * (cur0.x + cur1.x);
    mid01.y = 0.5f * (cur0.y + cur1.y);
    mid01.z = 0.5f * (cur0.z + cur1.z);
    mid01.w = 0.5f * (cur0.w + cur1.w);
    mid12.x = 0.5f * (cur1.x + nxt.x);
    mid12.y = 0.5f * (cur1.y + nxt.y);
    mid12.z = 0.5f * (cur1.z + nxt.z);
    mid12.w = 0.5f * (cur1.w + nxt.w);

    // output rows 4m .. 4m+3 (contiguous 4-row span)
    unsigned o = 4u * m * C4 + c;
    y[o]          = cur0;
    y[o + C4]     = mid01;
    y[o + 2u*C4]  = cur1;
    y[o + 3u*C4]  = mid12;
}

extern "C" void kernel_launch(void* const* d_in, const int* in_sizes, int n_in,
                              void* d_out, int out_size) {
    const float4* x = (const float4*)d_in[0];
    float4* y = (float4*)d_out;
    interp1d_kernel<<<TOTALT / 256, 256>>>(x, y);
}